// round 11
// baseline (speedup 1.0000x reference)
#include <cuda_runtime.h>
#include <cstdint>
#include <math.h>

#define EPSI 1e-5f

typedef unsigned long long u64t;

__device__ __forceinline__ u64t splat2(float a) {
    u64t r; asm("mov.b64 %0, {%1, %1};" : "=l"(r) : "f"(a)); return r;
}
__device__ __forceinline__ void fma2(u64t& d, u64t a, u64t b) {
    asm("fma.rn.f32x2 %0, %1, %2, %0;" : "+l"(d) : "l"(a), "l"(b));
}
__device__ __forceinline__ void unpack2(u64t v, float& lo, float& hi) {
    asm("mov.b64 {%0, %1}, %2;" : "=f"(lo), "=f"(hi) : "l"(v));
}
__device__ __forceinline__ void cp16(unsigned int dst, const void* src) {
    asm volatile("cp.async.cg.shared.global [%0], [%1], 16;" :: "r"(dst), "l"(src));
}

__device__ __forceinline__ float f4c(const float4& v, int i) {
    switch (i & 3) {
        case 0: return v.x;
        case 1: return v.y;
        case 2: return v.z;
        default: return v.w;
    }
}

// Full-width block GEMM: C[32 x 256] = A[32 x KTOT] (smem) * W[KTOT x 256].
// 512 threads, 16 warps = 2 row-groups x 8 col-groups.
// Warp (grp, w8): rows [16grp,+16), cols [16w8,+16) U [128+16w8,+16).
// Thread: rp=lane&3 -> 4 rows 16grp+rp+{0,4,8,12}; cp=lane>>2 -> c0=16w8+2cp.
// Per k: 8 FFMA2, 2 LDS.64 W (2.0 B/FFMA2). Warp-private W double buffer,
// no __syncthreads in mainloop (row-group warps duplicate cp.async traffic).
template <int KTOT, typename Epi>
__device__ __forceinline__ void gemm_tile(
    const float* __restrict__ As, int lda,
    const float* __restrict__ Wg, int ldw,
    float* __restrict__ wbuf, Epi epi)
{
    const int tid  = threadIdx.x;
    const int wid  = tid >> 5, lane = tid & 31;
    const int w8   = wid & 7, grp = wid >> 3;
    const int rp   = lane & 3, cp = lane >> 2;
    const int c0   = w8 * 16 + cp * 2;
    const int rbase = grp * 16 + rp;
    constexpr int NCH = KTOT / 16;

    float* wb = wbuf + wid * 1024;
    const unsigned int wb_s = (unsigned int)__cvta_generic_to_shared(wb);
    const int seg0 = lane >> 2;
    const int part = lane & 3;

    u64t acc[4][2];
#pragma unroll
    for (int i = 0; i < 4; i++) { acc[i][0] = 0ull; acc[i][1] = 0ull; }

    auto load_chunk = [&](int ch, int stage) {
        const float* Wr = Wg + ch * 16 * ldw + w8 * 16 + part * 4;
#pragma unroll
        for (int j = 0; j < 4; j++) {
            int seg = seg0 + 8 * j;
            int k = seg >> 1, half = seg & 1;
            cp16(wb_s + stage * 2048 + k * 128 + half * 64 + part * 16,
                 Wr + k * ldw + half * 128);
        }
        asm volatile("cp.async.commit_group;" ::: "memory");
    };

    load_chunk(0, 0);

    int cur = 0;
    for (int ch = 0; ch < NCH; ch++) {
        const bool more = (ch + 1 < NCH);
        if (more) {
            load_chunk(ch + 1, cur ^ 1);
            asm volatile("cp.async.wait_group 1;" ::: "memory");
        } else {
            asm volatile("cp.async.wait_group 0;" ::: "memory");
        }
        const float* wc = wb + cur * 512;
        const int kk = ch * 16;
#pragma unroll
        for (int k4 = 0; k4 < 4; k4++) {
            float4 a[4];
#pragma unroll
            for (int i = 0; i < 4; i++)
                a[i] = *reinterpret_cast<const float4*>(
                    As + (rbase + 4 * i) * lda + kk + k4 * 4);
#pragma unroll
            for (int kz = 0; kz < 4; kz++) {
                const float* wr = wc + (k4 * 4 + kz) * 32;
                u64t w0 = *reinterpret_cast<const u64t*>(wr + cp * 2);
                u64t w1 = *reinterpret_cast<const u64t*>(wr + 16 + cp * 2);
#pragma unroll
                for (int i = 0; i < 4; i++) {
                    u64t s = splat2(f4c(a[i], kz));
                    fma2(acc[i][0], s, w0);
                    fma2(acc[i][1], s, w1);
                }
            }
        }
        cur ^= 1;
    }
    epi(rbase, c0, acc);
}

// Half-width block GEMM: live output cols {0..63} U {128..191} only.
// 512 threads, 16 warps = 4 row-groups x 4 col-groups.
// Warp (grp4, w4): rows [8grp4,+8), cols [16w4,+16) U [128+16w4,+16).
// Thread: rp=lane&3 -> 2 rows 8grp4+rp+{0,4}; cp=lane>>2 -> c0=16w4+2cp.
template <int KTOT, typename Epi>
__device__ __forceinline__ void gemm_tile_half(
    const float* __restrict__ As, int lda,
    const float* __restrict__ Wg, int ldw,
    float* __restrict__ wbuf, Epi epi)
{
    const int tid  = threadIdx.x;
    const int wid  = tid >> 5, lane = tid & 31;
    const int w4   = wid & 3, grp4 = wid >> 2;
    const int rp   = lane & 3, cp = lane >> 2;
    const int c0   = w4 * 16 + cp * 2;
    const int rbase = grp4 * 8 + rp;
    constexpr int NCH = KTOT / 16;

    float* wb = wbuf + wid * 1024;
    const unsigned int wb_s = (unsigned int)__cvta_generic_to_shared(wb);
    const int seg0 = lane >> 2;
    const int part = lane & 3;

    u64t acc[2][2];
#pragma unroll
    for (int i = 0; i < 2; i++) { acc[i][0] = 0ull; acc[i][1] = 0ull; }

    auto load_chunk = [&](int ch, int stage) {
        const float* Wr = Wg + ch * 16 * ldw + w4 * 16 + part * 4;
#pragma unroll
        for (int j = 0; j < 4; j++) {
            int seg = seg0 + 8 * j;
            int k = seg >> 1, half = seg & 1;
            cp16(wb_s + stage * 2048 + k * 128 + half * 64 + part * 16,
                 Wr + k * ldw + half * 128);
        }
        asm volatile("cp.async.commit_group;" ::: "memory");
    };

    load_chunk(0, 0);

    int cur = 0;
    for (int ch = 0; ch < NCH; ch++) {
        const bool more = (ch + 1 < NCH);
        if (more) {
            load_chunk(ch + 1, cur ^ 1);
            asm volatile("cp.async.wait_group 1;" ::: "memory");
        } else {
            asm volatile("cp.async.wait_group 0;" ::: "memory");
        }
        const float* wc = wb + cur * 512;
        const int kk = ch * 16;
#pragma unroll
        for (int k4 = 0; k4 < 4; k4++) {
            float4 a[2];
#pragma unroll
            for (int i = 0; i < 2; i++)
                a[i] = *reinterpret_cast<const float4*>(
                    As + (rbase + 4 * i) * lda + kk + k4 * 4);
#pragma unroll
            for (int kz = 0; kz < 4; kz++) {
                const float* wr = wc + (k4 * 4 + kz) * 32;
                u64t w0 = *reinterpret_cast<const u64t*>(wr + cp * 2);
                u64t w1 = *reinterpret_cast<const u64t*>(wr + 16 + cp * 2);
#pragma unroll
                for (int i = 0; i < 2; i++) {
                    u64t s = splat2(f4c(a[i], kz));
                    fma2(acc[i][0], s, w0);
                    fma2(acc[i][1], s, w1);
                }
            }
        }
        cur ^= 1;
    }
    epi(rbase, c0, acc);
}

#define XS_LD 516
#define SH_LD 132
#define NTHREADS 512

__global__ __launch_bounds__(NTHREADS, 1)
void tabnet_kernel(
    const float* __restrict__ x,
    const float* __restrict__ bn0_g, const float* __restrict__ bn0_b,
    const float* __restrict__ bn0_m, const float* __restrict__ bn0_v,
    const float* __restrict__ shW,
    const float* __restrict__ sh_g, const float* __restrict__ sh_b,
    const float* __restrict__ sh_m, const float* __restrict__ sh_v,
    const float* __restrict__ stW,
    const float* __restrict__ st_g, const float* __restrict__ st_b,
    const float* __restrict__ st_m, const float* __restrict__ st_v,
    const float* __restrict__ fW, const float* __restrict__ fb,
    float* __restrict__ out)
{
    extern __shared__ float smem[];
    float* xs    = smem;             // [32][516]  x tile (GEMM1 A)
    float* shb   = smem + 16512;     // [32][132]  GLU(shared step) output
    float* aggs  = smem + 20736;     // [32][64]
    float* wbuf  = smem + 22784;     // 16 warps x 2 stages x 512 floats
    float* bnsc  = smem + 39168;     // [512]
    float* bnsh  = smem + 39680;     // [512]
    // total 40192 floats = 160768 bytes

    const int tid = threadIdx.x;
    const int row0 = blockIdx.x << 5;

    if (tid < 512) {
        int c = tid;
        float sc = bn0_g[c] * rsqrtf(bn0_v[c] + EPSI);
        bnsc[c] = sc;
        bnsh[c] = bn0_b[c] - bn0_m[c] * sc;
    }
    __syncthreads();

    // load x tile + bn0
    {
        const float4* xg = reinterpret_cast<const float4*>(x) + (size_t)row0 * 128;
        const float4* s4 = reinterpret_cast<const float4*>(bnsc);
        const float4* b4 = reinterpret_cast<const float4*>(bnsh);
        float4* xs4 = reinterpret_cast<float4*>(xs);
#pragma unroll
        for (int i = 0; i < 8; i++) {
            int f = tid + NTHREADS * i;
            int r = f >> 7, c4 = f & 127;
            float4 v = xg[f];
            float4 s = s4[c4], b = b4[c4];
            v.x = fmaf(v.x, s.x, b.x);
            v.y = fmaf(v.y, s.y, b.y);
            v.z = fmaf(v.z, s.z, b.z);
            v.w = fmaf(v.w, s.w, b.w);
            xs4[r * 129 + c4] = v;
        }
    }
    __syncthreads();

    // shared-step bn tables (256 cols)
    if (tid < 256) {
        int c = tid;
        float sc = sh_g[c] * rsqrtf(sh_v[c] + EPSI);
        bnsc[c] = sc;
        bnsh[c] = sh_b[c] - sh_m[c] * sc;
    }
    __syncthreads();

    // GEMM1: sh = GLU(bn(x @ shW))
    gemm_tile<512>(xs, XS_LD, shW, 256, wbuf,
        [&](int rb, int c0, u64t (&acc)[4][2]) {
#pragma unroll
            for (int i = 0; i < 4; i++) {
                int row = rb + 4 * i;
                float u[2], w[2];
                unpack2(acc[i][0], u[0], u[1]);
                unpack2(acc[i][1], w[0], w[1]);
#pragma unroll
                for (int t = 0; t < 2; t++) {
                    int cu = c0 + t, cw = c0 + 128 + t;
                    float uu = fmaf(u[t], bnsc[cu], bnsh[cu]);
                    float ww = fmaf(w[t], bnsc[cw], bnsh[cw]);
                    shb[row * SH_LD + cu] = uu / (1.f + __expf(-ww));
                }
            }
        });
    __syncthreads();

    // agg in registers: GEMM2 thread owns 2 rows x 2 cols (all cols < 64)
    float agg[2][2];
    agg[0][0] = agg[0][1] = agg[1][0] = agg[1][1] = 0.f;

    for (int s = 0; s < 3; s++) {
        if (tid < 256) {
            int c = tid;
            float sc = st_g[s * 256 + c] * rsqrtf(st_v[s * 256 + c] + EPSI);
            bnsc[c] = sc;
            bnsh[c] = st_b[s * 256 + c] - st_m[s * 256 + c] * sc;
        }
        __syncthreads();
        // GEMM2 (half): h_d = GLU(bn(sh @ stW[s]))[:, :64]; agg += h_d
        gemm_tile_half<128>(shb, SH_LD, stW + s * 128 * 256, 256, wbuf,
            [&](int rb, int c0, u64t (&acc)[2][2]) {
#pragma unroll
                for (int i = 0; i < 2; i++) {
                    float u[2], w[2];
                    unpack2(acc[i][0], u[0], u[1]);
                    unpack2(acc[i][1], w[0], w[1]);
#pragma unroll
                    for (int t = 0; t < 2; t++) {
                        int cu = c0 + t, cw = c0 + 128 + t;
                        float uu = fmaf(u[t], bnsc[cu], bnsh[cu]);
                        float ww = fmaf(w[t], bnsc[cw], bnsh[cw]);
                        agg[i][t] += uu / (1.f + __expf(-ww));
                    }
                }
            });
        __syncthreads();
    }

    // write agg registers to smem (ownership matches gemm_tile_half layout)
    {
        const int wid = tid >> 5, lane = tid & 31;
        const int w4 = wid & 3, grp4 = wid >> 2;
        const int rp = lane & 3, cp = lane >> 2;
        const int c0 = w4 * 16 + cp * 2;
        const int rb = grp4 * 8 + rp;
#pragma unroll
        for (int i = 0; i < 2; i++) {
            aggs[(rb + 4 * i) * 64 + c0]     = agg[i][0];
            aggs[(rb + 4 * i) * 64 + c0 + 1] = agg[i][1];
        }
    }
    __syncthreads();

    // final: out = agg @ fW + fb
    if (tid < 64) {
        int m = tid >> 1, o = tid & 1;
        float acc = fb[o];
#pragma unroll
        for (int j = 0; j < 64; j++) acc = fmaf(aggs[m * 64 + j], fW[j * 2 + o], acc);
        out[(size_t)(row0 + m) * 2 + o] = acc;
    }
}

extern "C" void kernel_launch(void* const* d_in, const int* in_sizes, int n_in,
                              void* d_out, int out_size)
{
    const float* x    = (const float*)d_in[0];
    const float* bn0g = (const float*)d_in[1];
    const float* bn0b = (const float*)d_in[2];
    const float* bn0m = (const float*)d_in[3];
    const float* bn0v = (const float*)d_in[4];
    const float* shW  = (const float*)d_in[5];
    const float* shg  = (const float*)d_in[6];
    const float* shbp = (const float*)d_in[7];
    const float* shm  = (const float*)d_in[8];
    const float* shv  = (const float*)d_in[9];
    const float* stW  = (const float*)d_in[10];
    const float* stg  = (const float*)d_in[11];
    const float* stb  = (const float*)d_in[12];
    const float* stm  = (const float*)d_in[13];
    const float* stv  = (const float*)d_in[14];
    const float* fW   = (const float*)d_in[20];
    const float* fb   = (const float*)d_in[21];

    int Btot = in_sizes[0] / 512;
    int grid = Btot / 32;
    size_t smem = 40192 * sizeof(float);
    cudaFuncSetAttribute(tabnet_kernel,
                         cudaFuncAttributeMaxDynamicSharedMemorySize, (int)smem);
    tabnet_kernel<<<grid, NTHREADS, smem>>>(
        x, bn0g, bn0b, bn0m, bn0v,
        shW, shg, shbp, shm, shv,
        stW, stg, stb, stm, stv,
        fW, fb, (float*)d_out);
}

// round 12
// speedup vs baseline: 1.2764x; 1.2764x over previous
#include <cuda_runtime.h>
#include <cstdint>
#include <math.h>

#define EPSI 1e-5f

typedef unsigned long long u64t;

__device__ __forceinline__ u64t splat2(float a) {
    u64t r; asm("mov.b64 %0, {%1, %1};" : "=l"(r) : "f"(a)); return r;
}
__device__ __forceinline__ void fma2(u64t& d, u64t a, u64t b) {
    asm("fma.rn.f32x2 %0, %1, %2, %0;" : "+l"(d) : "l"(a), "l"(b));
}
__device__ __forceinline__ void unpack2(u64t v, float& lo, float& hi) {
    asm("mov.b64 {%0, %1}, %2;" : "=f"(lo), "=f"(hi) : "l"(v));
}
__device__ __forceinline__ void cp16(unsigned int dst, const void* src) {
    asm volatile("cp.async.cg.shared.global [%0], [%1], 16;" :: "r"(dst), "l"(src));
}

__device__ __forceinline__ float f4c(const float4& v, int i) {
    switch (i & 3) {
        case 0: return v.x;
        case 1: return v.y;
        case 2: return v.z;
        default: return v.w;
    }
}

// Full-width block GEMM (accumulate-only): C[32x256] += A[32xKTOT] * W[KTOT x 256].
// 256 threads, 8 warps. Warp w owns cols [16w,+16) U [128+16w,+16) (GLU pairs in-warp).
// Warp-private W smem double buffer via own cp.async groups: NO __syncthreads inside.
// Thread tile 8 rows x 4 cols; per k: 16 FFMA2, 2 LDS.64 W (2.0 B/FFMA2, no duplication).
// acc passed by reference so K can be split across multiple calls (x-tile reuse).
template <int KTOT>
__device__ __forceinline__ void gemm_tile_acc(
    const float* __restrict__ As, int lda,
    const float* __restrict__ Wg, int ldw,
    float* __restrict__ wbuf, u64t (&acc)[8][2])
{
    const int tid  = threadIdx.x;
    const int wid  = tid >> 5, lane = tid & 31;
    const int rp   = lane & 3, cp = lane >> 2;
    constexpr int NCH = KTOT / 16;

    float* wb = wbuf + wid * 1024;
    const unsigned int wb_s = (unsigned int)__cvta_generic_to_shared(wb);
    const int seg0 = lane >> 2;
    const int part = lane & 3;

    auto load_chunk = [&](int ch, int stage) {
        const float* Wr = Wg + ch * 16 * ldw + wid * 16 + part * 4;
#pragma unroll
        for (int j = 0; j < 4; j++) {
            int seg = seg0 + 8 * j;
            int k = seg >> 1, half = seg & 1;
            cp16(wb_s + stage * 2048 + k * 128 + half * 64 + part * 16,
                 Wr + k * ldw + half * 128);
        }
        asm volatile("cp.async.commit_group;" ::: "memory");
    };

    load_chunk(0, 0);

    int cur = 0;
    for (int ch = 0; ch < NCH; ch++) {
        const bool more = (ch + 1 < NCH);
        if (more) {
            load_chunk(ch + 1, cur ^ 1);
            asm volatile("cp.async.wait_group 1;" ::: "memory");
        } else {
            asm volatile("cp.async.wait_group 0;" ::: "memory");
        }
        const float* wc = wb + cur * 512;
        const int kk = ch * 16;
#pragma unroll
        for (int k4 = 0; k4 < 4; k4++) {
            float4 a[8];
#pragma unroll
            for (int i = 0; i < 8; i++)
                a[i] = *reinterpret_cast<const float4*>(
                    As + (rp + 4 * i) * lda + kk + k4 * 4);
#pragma unroll
            for (int kz = 0; kz < 4; kz++) {
                const float* wr = wc + (k4 * 4 + kz) * 32;
                u64t w0 = *reinterpret_cast<const u64t*>(wr + cp * 2);
                u64t w1 = *reinterpret_cast<const u64t*>(wr + 16 + cp * 2);
#pragma unroll
                for (int i = 0; i < 8; i++) {
                    u64t s = splat2(f4c(a[i], kz));
                    fma2(acc[i][0], s, w0);
                    fma2(acc[i][1], s, w1);
                }
            }
        }
        cur ^= 1;
    }
}

// Half-width block GEMM: live output cols {0..63} U {128..191} only.
// 8 warps = 2 row-groups x 4 col-groups. Thread tile 4 rows x 4 cols.
template <int KTOT, typename Epi>
__device__ __forceinline__ void gemm_tile_half(
    const float* __restrict__ As, int lda,
    const float* __restrict__ Wg, int ldw,
    float* __restrict__ wbuf, Epi epi)
{
    const int tid  = threadIdx.x;
    const int wid  = tid >> 5, lane = tid & 31;
    const int w4   = wid & 3, grp = wid >> 2;
    const int rp   = lane & 3, cp = lane >> 2;
    const int c0   = w4 * 16 + cp * 2;
    const int rbase = grp * 16 + rp;
    constexpr int NCH = KTOT / 16;

    float* wb = wbuf + wid * 1024;
    const unsigned int wb_s = (unsigned int)__cvta_generic_to_shared(wb);
    const int seg0 = lane >> 2;
    const int part = lane & 3;

    u64t acc[4][2];
#pragma unroll
    for (int i = 0; i < 4; i++) { acc[i][0] = 0ull; acc[i][1] = 0ull; }

    auto load_chunk = [&](int ch, int stage) {
        const float* Wr = Wg + ch * 16 * ldw + w4 * 16 + part * 4;
#pragma unroll
        for (int j = 0; j < 4; j++) {
            int seg = seg0 + 8 * j;
            int k = seg >> 1, half = seg & 1;
            cp16(wb_s + stage * 2048 + k * 128 + half * 64 + part * 16,
                 Wr + k * ldw + half * 128);
        }
        asm volatile("cp.async.commit_group;" ::: "memory");
    };

    load_chunk(0, 0);

    int cur = 0;
    for (int ch = 0; ch < NCH; ch++) {
        const bool more = (ch + 1 < NCH);
        if (more) {
            load_chunk(ch + 1, cur ^ 1);
            asm volatile("cp.async.wait_group 1;" ::: "memory");
        } else {
            asm volatile("cp.async.wait_group 0;" ::: "memory");
        }
        const float* wc = wb + cur * 512;
        const int kk = ch * 16;
#pragma unroll
        for (int k4 = 0; k4 < 4; k4++) {
            float4 a[4];
#pragma unroll
            for (int i = 0; i < 4; i++)
                a[i] = *reinterpret_cast<const float4*>(
                    As + (rbase + 4 * i) * lda + kk + k4 * 4);
#pragma unroll
            for (int kz = 0; kz < 4; kz++) {
                const float* wr = wc + (k4 * 4 + kz) * 32;
                u64t w0 = *reinterpret_cast<const u64t*>(wr + cp * 2);
                u64t w1 = *reinterpret_cast<const u64t*>(wr + 16 + cp * 2);
#pragma unroll
                for (int i = 0; i < 4; i++) {
                    u64t s = splat2(f4c(a[i], kz));
                    fma2(acc[i][0], s, w0);
                    fma2(acc[i][1], s, w1);
                }
            }
        }
        cur ^= 1;
    }
    epi(rbase, c0, acc);
}

#define XH_LD 260
#define SH_LD 132

__global__ __launch_bounds__(256, 2)
void tabnet_kernel(
    const float* __restrict__ x,
    const float* __restrict__ bn0_g, const float* __restrict__ bn0_b,
    const float* __restrict__ bn0_m, const float* __restrict__ bn0_v,
    const float* __restrict__ shW,
    const float* __restrict__ sh_g, const float* __restrict__ sh_b,
    const float* __restrict__ sh_m, const float* __restrict__ sh_v,
    const float* __restrict__ stW,
    const float* __restrict__ st_g, const float* __restrict__ st_b,
    const float* __restrict__ st_m, const float* __restrict__ st_v,
    const float* __restrict__ fW, const float* __restrict__ fb,
    float* __restrict__ out)
{
    extern __shared__ float smem[];
    float* xsh   = smem;             // [32][260] x K-half tile
    float* shb   = smem + 8320;      // [32][132] GLU(shared step) output
    float* aggs  = smem + 12544;     // [32][64]
    float* wbuf  = smem + 14592;     // 8 warps x 2 stages x 512
    float* bn0sc = smem + 22784;     // [512]
    float* bn0sh = smem + 23296;     // [512]
    float* sbnsc = smem + 23808;     // [256] shared/step bn tables
    float* sbnsh = smem + 24064;     // [256]
    // total 24320 floats = 97280 bytes -> 2 blocks/SM

    const int tid = threadIdx.x;
    const int row0 = blockIdx.x << 5;

    for (int c = tid; c < 512; c += 256) {
        float sc = bn0_g[c] * rsqrtf(bn0_v[c] + EPSI);
        bn0sc[c] = sc;
        bn0sh[c] = bn0_b[c] - bn0_m[c] * sc;
    }
    __syncthreads();

    // GEMM1 accumulators persist across the two K-halves
    u64t acc1[8][2];
#pragma unroll
    for (int i = 0; i < 8; i++) { acc1[i][0] = 0ull; acc1[i][1] = 0ull; }

    for (int h = 0; h < 2; h++) {
        if (h) __syncthreads();   // all warps done reading previous x half
        // load x half h (cols [256h, 256h+256)) + bn0
        {
            const float4* xg = reinterpret_cast<const float4*>(x)
                             + (size_t)row0 * 128 + h * 64;
            const float4* s4 = reinterpret_cast<const float4*>(bn0sc) + h * 64;
            const float4* b4 = reinterpret_cast<const float4*>(bn0sh) + h * 64;
            float4* xs4 = reinterpret_cast<float4*>(xsh);
#pragma unroll
            for (int i = 0; i < 8; i++) {
                int f = tid + 256 * i;
                int r = f >> 6, c4 = f & 63;
                float4 v = xg[r * 128 + c4];
                float4 s = s4[c4], b = b4[c4];
                v.x = fmaf(v.x, s.x, b.x);
                v.y = fmaf(v.y, s.y, b.y);
                v.z = fmaf(v.z, s.z, b.z);
                v.w = fmaf(v.w, s.w, b.w);
                xs4[r * 65 + c4] = v;
            }
        }
        if (h == 1) {
            // shared-step bn tables (needed only by the epilogue after half 2)
            int c = tid;
            float sc = sh_g[c] * rsqrtf(sh_v[c] + EPSI);
            sbnsc[c] = sc;
            sbnsh[c] = sh_b[c] - sh_m[c] * sc;
        }
        __syncthreads();
        gemm_tile_acc<256>(xsh, XH_LD, shW + h * 256 * 256, 256, wbuf, acc1);
    }

    // GEMM1 epilogue: sh = GLU(bn(.))
    {
        const int wid = tid >> 5, lane = tid & 31;
        const int rp = lane & 3, cp = lane >> 2;
        const int c0 = wid * 16 + cp * 2;
#pragma unroll
        for (int i = 0; i < 8; i++) {
            int row = rp + 4 * i;
            float u[2], w[2];
            unpack2(acc1[i][0], u[0], u[1]);
            unpack2(acc1[i][1], w[0], w[1]);
#pragma unroll
            for (int t = 0; t < 2; t++) {
                int cu = c0 + t, cw = c0 + 128 + t;
                float uu = fmaf(u[t], sbnsc[cu], sbnsh[cu]);
                float ww = fmaf(w[t], sbnsc[cw], sbnsh[cw]);
                shb[row * SH_LD + cu] = uu / (1.f + __expf(-ww));
            }
        }
    }
    __syncthreads();

    // agg accumulated in registers: thread owns 4 rows x 2 cols (all cols < 64)
    float agg[4][2];
#pragma unroll
    for (int i = 0; i < 4; i++) { agg[i][0] = 0.f; agg[i][1] = 0.f; }

    for (int s = 0; s < 3; s++) {
        {
            int c = tid;
            float sc = st_g[s * 256 + c] * rsqrtf(st_v[s * 256 + c] + EPSI);
            sbnsc[c] = sc;
            sbnsh[c] = st_b[s * 256 + c] - st_m[s * 256 + c] * sc;
        }
        __syncthreads();
        // GEMM2 (half): h_d = GLU(bn(sh @ stW[s]))[:, :64]; agg += h_d
        gemm_tile_half<128>(shb, SH_LD, stW + s * 128 * 256, 256, wbuf,
            [&](int rb, int c0, u64t (&acc)[4][2]) {
#pragma unroll
                for (int i = 0; i < 4; i++) {
                    float u[2], w[2];
                    unpack2(acc[i][0], u[0], u[1]);
                    unpack2(acc[i][1], w[0], w[1]);
#pragma unroll
                    for (int t = 0; t < 2; t++) {
                        int cu = c0 + t, cw = c0 + 128 + t;
                        float uu = fmaf(u[t], sbnsc[cu], sbnsh[cu]);
                        float ww = fmaf(w[t], sbnsc[cw], sbnsh[cw]);
                        agg[i][t] += uu / (1.f + __expf(-ww));
                    }
                }
            });
        __syncthreads();
    }

    // write agg registers to smem (ownership matches gemm_tile_half layout)
    {
        const int wid = tid >> 5, lane = tid & 31;
        const int w4 = wid & 3, grp = wid >> 2;
        const int rp = lane & 3, cp = lane >> 2;
        const int c0 = w4 * 16 + cp * 2;
        const int rb = grp * 16 + rp;
#pragma unroll
        for (int i = 0; i < 4; i++) {
            aggs[(rb + 4 * i) * 64 + c0]     = agg[i][0];
            aggs[(rb + 4 * i) * 64 + c0 + 1] = agg[i][1];
        }
    }
    __syncthreads();

    // final: out = agg @ fW + fb
    if (tid < 64) {
        int m = tid >> 1, o = tid & 1;
        float acc = fb[o];
#pragma unroll
        for (int j = 0; j < 64; j++) acc = fmaf(aggs[m * 64 + j], fW[j * 2 + o], acc);
        out[(size_t)(row0 + m) * 2 + o] = acc;
    }
}

extern "C" void kernel_launch(void* const* d_in, const int* in_sizes, int n_in,
                              void* d_out, int out_size)
{
    const float* x    = (const float*)d_in[0];
    const float* bn0g = (const float*)d_in[1];
    const float* bn0b = (const float*)d_in[2];
    const float* bn0m = (const float*)d_in[3];
    const float* bn0v = (const float*)d_in[4];
    const float* shW  = (const float*)d_in[5];
    const float* shg  = (const float*)d_in[6];
    const float* shbp = (const float*)d_in[7];
    const float* shm  = (const float*)d_in[8];
    const float* shv  = (const float*)d_in[9];
    const float* stW  = (const float*)d_in[10];
    const float* stg  = (const float*)d_in[11];
    const float* stb  = (const float*)d_in[12];
    const float* stm  = (const float*)d_in[13];
    const float* stv  = (const float*)d_in[14];
    const float* fW   = (const float*)d_in[20];
    const float* fb   = (const float*)d_in[21];

    int Btot = in_sizes[0] / 512;
    int grid = Btot / 32;
    size_t smem = 24320 * sizeof(float);
    cudaFuncSetAttribute(tabnet_kernel,
                         cudaFuncAttributeMaxDynamicSharedMemorySize, (int)smem);
    tabnet_kernel<<<grid, 256, smem>>>(
        x, bn0g, bn0b, bn0m, bn0v,
        shW, shg, shbp, shm, shv,
        stW, stg, stb, stm, stv,
        fW, fb, (float*)d_out);
}